// round 3
// baseline (speedup 1.0000x reference)
#include <cuda_runtime.h>
#include <cuda_bf16.h>

#define HID   64
#define NFLD  2
#define NHH   32
#define NMF   8
#define NTS   4
#define NLAY  9          // hidden (relu,linear) layers in edge MLP
#define MAXN  10016

// ---------------- scratch (device globals; no allocation allowed) -----------
__device__ float g_Ptop[MAXN * HID];
__device__ float g_Pbot[MAXN * HID];
__device__ float g_acc [MAXN * HID];
__device__ float g_meshh[MAXN * NHH];
__device__ float g_henc[MAXN * HID];
__device__ float g_Fprev[MAXN * NFLD];

// ---------------- packed fp32 helpers (FFMA2 path) ---------------------------
__device__ __forceinline__ unsigned long long pack2(float x, float y) {
    unsigned long long r;
    asm("mov.b64 %0, {%1, %2};" : "=l"(r) : "f"(x), "f"(y));
    return r;
}
__device__ __forceinline__ float2 unpack2(unsigned long long v) {
    float2 r;
    asm("mov.b64 {%0, %1}, %2;" : "=f"(r.x), "=f"(r.y) : "l"(v));
    return r;
}
__device__ __forceinline__ void ffma2(unsigned long long& d,
                                      unsigned long long a, unsigned long long b) {
    asm("fma.rn.f32x2 %0, %1, %2, %0;" : "+l"(d) : "l"(a), "l"(b));
}
__device__ __forceinline__ void red4(float* p, float a, float b, float c, float d) {
    asm volatile("red.global.add.v4.f32 [%0], {%1, %2, %3, %4};"
                 :: "l"(p), "f"(a), "f"(b), "f"(c), "f"(d) : "memory");
}

// ---------------- per-node projection for mesh-descriptor pass --------------
__global__ void proj_md_kernel(const float* __restrict__ X,
                               const float* __restrict__ W0,
                               float* __restrict__ Ptop, float* __restrict__ Pbot,
                               float* __restrict__ acc, int Nn)
{
    int idx = blockIdx.x * blockDim.x + threadIdx.x;
    if (idx >= Nn * HID) return;
    int n = idx >> 6, j = idx & 63;
    float st = 0.f, sb = 0.f;
#pragma unroll
    for (int k = 0; k < NMF; k++) {
        float x = X[n * NMF + k];
        st = fmaf(x, W0[k * HID + j], st);
        sb = fmaf(x, W0[(NMF + k) * HID + j], sb);
    }
    Ptop[idx] = st;
    Pbot[idx] = sb;
    acc[idx]  = 0.f;
}

// ---------------- node encoder for derivative solver ------------------------
__global__ void enc_ds_kernel(const float* __restrict__ meshh,
                              const float* __restrict__ Fprev,
                              const float* __restrict__ Fb, int t,
                              const float* __restrict__ W,
                              const float* __restrict__ b,
                              float* __restrict__ henc, int Nn)
{
    int idx = blockIdx.x * blockDim.x + threadIdx.x;
    if (idx >= Nn * HID) return;
    int n = idx >> 6, j = idx & 63;
    float s = b[j];
#pragma unroll
    for (int k = 0; k < NHH; k++)
        s = fmaf(meshh[n * NHH + k], W[k * HID + j], s);
    s = fmaf(Fprev[n * NFLD + 0], W[(NHH + 0) * HID + j], s);
    s = fmaf(Fprev[n * NFLD + 1], W[(NHH + 1) * HID + j], s);
    s = fmaf(Fb[n * NTS + t],     W[(NHH + 2) * HID + j], s);
    henc[idx] = fmaxf(s, 0.f);
}

// ---------------- per-node projection for ds pass ---------------------------
__global__ void proj_ds_kernel(const float* __restrict__ Xh,
                               const float* __restrict__ W0,
                               float* __restrict__ Ptop, float* __restrict__ Pbot,
                               float* __restrict__ acc, int Nn)
{
    int idx = blockIdx.x * blockDim.x + threadIdx.x;
    if (idx >= Nn * HID) return;
    int n = idx >> 6, j = idx & 63;
    float st = 0.f, sb = 0.f;
#pragma unroll 8
    for (int k = 0; k < HID; k++) {
        float x = Xh[n * HID + k];
        st = fmaf(x, W0[k * HID + j], st);
        sb = fmaf(x, W0[(HID + k) * HID + j], sb);
    }
    Ptop[idx] = st;
    Pbot[idx] = sb;
    acc[idx]  = 0.f;
}

// ---------------- fused edge MLP + scatter -----------------------------------
// Tile: 128 edges x 64 hidden, 256 threads; thread tile = 8 edges (4 packed
// pairs) x 4 cols.  A0 = relu(Ptop[dst]+Pbot[src]+b0); 9 x {64x64 linear via
// FFMA2, relu at store except last}.  Weights pre-duplicated in smem as
// (w,w) pairs so the k-loop has ZERO mov duplication: 16 FFMA2 + 4 LDS.128/k.
// Next layer's W is LDG-prefetched into registers during compute.
// dyn smem: A ping/pong 2*64*128 + Wdup 64*128 floats = 98304 B.
__global__ void __launch_bounds__(256, 2)
edge_mlp_kernel(const float* __restrict__ Ptop, const float* __restrict__ Pbot,
                const float* __restrict__ b0,
                const float* __restrict__ Wh,  // (9,64,64)
                const float* __restrict__ Bh,  // (9,64)
                const int* __restrict__ src, const int* __restrict__ dst,
                float* __restrict__ acc, int E)
{
    extern __shared__ float smem[];
    float* A0   = smem;                 // [64][128]
    float* A1   = smem + 64 * 128;      // [64][128]
    float* Wdup = smem + 2 * 64 * 128;  // [64][128] (pairs (w,w) per col)

    const int tid = threadIdx.x;
    const int ep  = tid & 15;          // edge octet: edges ep*8 .. ep*8+7
    const int tj  = tid >> 4;          // col quad:  cols  tj*4 .. tj*4+3
    const int e0  = blockIdx.x * 128;

    // ---- prologue: gather h0 = relu(Ptop[dst]+Pbot[src]+b0) into A0[k][e] ----
    for (int i = tid; i < 128 * 16; i += 256) {
        int kq = i >> 7;            // float4 group 0..15 (uniform within warp)
        int e  = i & 127;           // edge (consecutive lanes)
        int ge = e0 + e;
        float4 vt = make_float4(0.f, 0.f, 0.f, 0.f);
        float4 vb = make_float4(0.f, 0.f, 0.f, 0.f);
        if (ge < E) {
            int d = dst[ge], s = src[ge];
            vt = *(const float4*)(Ptop + d * HID + kq * 4);
            vb = *(const float4*)(Pbot + s * HID + kq * 4);
        }
        float4 bb = *(const float4*)(b0 + kq * 4);
        int k = kq * 4;
        A0[(k + 0) * 128 + e] = fmaxf(vt.x + vb.x + bb.x, 0.f);
        A0[(k + 1) * 128 + e] = fmaxf(vt.y + vb.y + bb.y, 0.f);
        A0[(k + 2) * 128 + e] = fmaxf(vt.z + vb.z + bb.z, 0.f);
        A0[(k + 3) * 128 + e] = fmaxf(vt.w + vb.w + bb.w, 0.f);
    }

    // ---- W staging helpers: each thread owns 16 consecutive W elements ------
    // flat pos p = tid*16 + i  ->  k = p>>6 (constant per thread), j = p&63.
    const int wk = (tid * 16) >> 6;       // k row owned by this thread
    const int wj = (tid * 16) & 63;       // starting col
    float4 wreg[4];

    // load layer-0 weights into regs, then store duplicated
    {
        const float4* Wg = (const float4*)(Wh + 0 * HID * HID);
#pragma unroll
        for (int i = 0; i < 4; i++) wreg[i] = Wg[tid * 4 + i];
#pragma unroll
        for (int i = 0; i < 4; i++) {
            float4 w = wreg[i];
            float* dst0 = Wdup + (wk << 7) + 2 * (wj + i * 4);
            *(float4*)(dst0    ) = make_float4(w.x, w.x, w.y, w.y);
            *(float4*)(dst0 + 4) = make_float4(w.z, w.z, w.w, w.w);
        }
    }
    __syncthreads();   // A0 + Wdup(layer 0) ready

    float* Acur = A0;
    float* Anxt = A1;

    for (int l = 0; l < NLAY; l++) {
        // prefetch next layer's weights into registers (latency hidden)
        if (l + 1 < NLAY) {
            const float4* Wg = (const float4*)(Wh + (l + 1) * HID * HID);
#pragma unroll
            for (int i = 0; i < 4; i++) wreg[i] = Wg[tid * 4 + i];
        }

        // bias init: packed (b_j, b_j) replicated over the 4 edge-pairs
        unsigned long long acc2[4][4];
#pragma unroll
        for (int c = 0; c < 4; c++) {
            float bj = Bh[l * HID + (tj << 2) + c];
            unsigned long long bp = pack2(bj, bj);
#pragma unroll
            for (int p = 0; p < 4; p++) acc2[p][c] = bp;
        }

#pragma unroll 16
        for (int k = 0; k < HID; k++) {
            ulonglong2 a01 = *(const ulonglong2*)(Acur + (k << 7) + (ep << 3));
            ulonglong2 a23 = *(const ulonglong2*)(Acur + (k << 7) + (ep << 3) + 4);
            ulonglong2 w01 = *(const ulonglong2*)(Wdup + (k << 7) + (tj << 3));
            ulonglong2 w23 = *(const ulonglong2*)(Wdup + (k << 7) + (tj << 3) + 4);
            unsigned long long ap[4] = {a01.x, a01.y, a23.x, a23.y};
            unsigned long long wp[4] = {w01.x, w01.y, w23.x, w23.y};
#pragma unroll
            for (int p = 0; p < 4; p++)
#pragma unroll
                for (int c = 0; c < 4; c++)
                    ffma2(acc2[p][c], ap[p], wp[c]);
        }

        // write next activations [j][e]; packed pair = 2 consecutive edges
        const bool dorelu = (l != NLAY - 1);
#pragma unroll
        for (int c = 0; c < 4; c++) {
            int j = (tj << 2) + c;
#pragma unroll
            for (int p = 0; p < 4; p++) {
                float2 v = unpack2(acc2[p][c]);
                if (dorelu) { v.x = fmaxf(v.x, 0.f); v.y = fmaxf(v.y, 0.f); }
                *(float2*)(Anxt + (j << 7) + (ep << 3) + 2 * p) = v;
            }
        }

        __syncthreads();   // all reads of Acur/Wdup done; Anxt written

        if (l + 1 < NLAY) {
#pragma unroll
            for (int i = 0; i < 4; i++) {
                float4 w = wreg[i];
                float* dst0 = Wdup + (wk << 7) + 2 * (wj + i * 4);
                *(float4*)(dst0    ) = make_float4(w.x, w.x, w.y, w.y);
                *(float4*)(dst0 + 4) = make_float4(w.z, w.z, w.w, w.w);
            }
        }
        __syncthreads();   // Wdup(l+1) ready; Anxt visible to all

        float* t = Acur; Acur = Anxt; Anxt = t;
    }

    // ---- epilogue: segment-sum scatter by src (vector red) ----
    int e    = tid >> 1;
    int half = tid & 1;
    int ge   = e0 + e;
    if (ge < E) {
        int node = src[ge];
        float* ap = acc + node * HID + half * 32;
#pragma unroll
        for (int kk = 0; kk < 32; kk += 4) {
            float v0 = Acur[((half * 32 + kk + 0) << 7) + e];
            float v1 = Acur[((half * 32 + kk + 1) << 7) + e];
            float v2 = Acur[((half * 32 + kk + 2) << 7) + e];
            float v3 = Acur[((half * 32 + kk + 3) << 7) + e];
            red4(ap + kk, v0, v1, v2, v3);
        }
    }
}

// ---------------- node decoder (mesh descriptor) -----------------------------
__global__ void dec_md_kernel(const float* __restrict__ acc,
                              const float* __restrict__ dw1, const float* __restrict__ db1,
                              const float* __restrict__ dw2, const float* __restrict__ db2,
                              float* __restrict__ meshh, int Nn)
{
    __shared__ float t1[4][64];
    int tid = threadIdx.x;
    int q = tid >> 6, j = tid & 63;
    int n = blockIdx.x * 4 + q;
    float s = db1[j];
    if (n < Nn) {
#pragma unroll 8
        for (int k = 0; k < HID; k++)
            s = fmaf(acc[n * HID + k], dw1[k * HID + j], s);
    }
    t1[q][j] = fmaxf(s, 0.f);
    __syncthreads();
    if (tid < 128) {
        int q2 = tid >> 5, j2 = tid & 31;
        int n2 = blockIdx.x * 4 + q2;
        if (n2 < Nn) {
            float o = db2[j2];
#pragma unroll 8
            for (int k = 0; k < HID; k++)
                o = fmaf(t1[q2][k], dw2[k * NHH + j2], o);
            meshh[n2 * NHH + j2] = o;
        }
    }
}

// ---------------- node decoder (ds) + Euler step + output --------------------
__global__ void dec_ds_kernel(const float* __restrict__ acc,
                              const float* __restrict__ dw1, const float* __restrict__ db1,
                              const float* __restrict__ dw2, const float* __restrict__ db2,
                              const float* __restrict__ Fprev_in,
                              const float* __restrict__ dtp,
                              float* __restrict__ Fprev_out,
                              float* __restrict__ outF, float* __restrict__ outFd,
                              int step, int nsteps, int Nn)
{
    __shared__ float t1[4][64];
    int tid = threadIdx.x;
    int q = tid >> 6, j = tid & 63;
    int n = blockIdx.x * 4 + q;
    float s = db1[j];
    if (n < Nn) {
#pragma unroll 8
        for (int k = 0; k < HID; k++)
            s = fmaf(acc[n * HID + k], dw1[k * HID + j], s);
    }
    t1[q][j] = fmaxf(s, 0.f);
    __syncthreads();
    if (tid < 8) {
        int q2 = tid >> 1, f = tid & 1;
        int n2 = blockIdx.x * 4 + q2;
        if (n2 < Nn) {
            float o = db2[f];
#pragma unroll 8
            for (int k = 0; k < HID; k++)
                o = fmaf(t1[q2][k], dw2[k * NFLD + f], o);
            float fp = Fprev_in[n2 * NFLD + f];
            float fc = fmaf(dtp[0], o, fp);
            outF [(n2 * nsteps + step) * NFLD + f] = fc;
            outFd[(n2 * nsteps + step) * NFLD + f] = o;
            Fprev_out[n2 * NFLD + f] = fc;
        }
    }
}

// ---------------- launch ------------------------------------------------------
extern "C" void kernel_launch(void* const* d_in, const int* in_sizes, int n_in,
                              void* d_out, int out_size)
{
    const float* F_initial     = (const float*)d_in[0];
    const float* mesh_features = (const float*)d_in[1];
    const int*   edge_index    = (const int*)  d_in[2];
    const float* F_boundary    = (const float*)d_in[3];
    const float* dtp           = (const float*)d_in[4];
    const float* md_w0  = (const float*)d_in[5];
    const float* md_b0  = (const float*)d_in[6];
    const float* md_wh  = (const float*)d_in[7];
    const float* md_bh  = (const float*)d_in[8];
    const float* md_dw1 = (const float*)d_in[9];
    const float* md_db1 = (const float*)d_in[10];
    const float* md_dw2 = (const float*)d_in[11];
    const float* md_db2 = (const float*)d_in[12];
    const float* ds_encw = (const float*)d_in[13];
    const float* ds_encb = (const float*)d_in[14];
    const float* ds_w0  = (const float*)d_in[15];
    const float* ds_b0  = (const float*)d_in[16];
    const float* ds_wh  = (const float*)d_in[17];
    const float* ds_bh  = (const float*)d_in[18];
    const float* ds_dw1 = (const float*)d_in[19];
    const float* ds_db1 = (const float*)d_in[20];
    const float* ds_dw2 = (const float*)d_in[21];
    const float* ds_db2 = (const float*)d_in[22];

    int Nn = in_sizes[0] / NFLD;
    int E  = in_sizes[2] / 2;

    float *Ptop, *Pbot, *acc, *meshh, *henc, *Fprev;
    cudaGetSymbolAddress((void**)&Ptop,  g_Ptop);
    cudaGetSymbolAddress((void**)&Pbot,  g_Pbot);
    cudaGetSymbolAddress((void**)&acc,   g_acc);
    cudaGetSymbolAddress((void**)&meshh, g_meshh);
    cudaGetSymbolAddress((void**)&henc,  g_henc);
    cudaGetSymbolAddress((void**)&Fprev, g_Fprev);

    const size_t SMEM = (size_t)(2 * 64 * 128 + 64 * 128) * sizeof(float);  // 98304
    cudaFuncSetAttribute(edge_mlp_kernel,
                         cudaFuncAttributeMaxDynamicSharedMemorySize, (int)SMEM);

    const int* srcp = edge_index;
    const int* dstp = edge_index + E;

    int nb_node = (Nn * HID + 255) / 256;
    int nb_edge = (E + 127) / 128;
    int nb_dec  = (Nn + 3) / 4;
    int nsteps  = NTS - 1;

    float* outF  = (float*)d_out;
    float* outFd = outF + (size_t)out_size / 2;

    // ---- mesh descriptor pass ----
    proj_md_kernel<<<nb_node, 256>>>(mesh_features, md_w0, Ptop, Pbot, acc, Nn);
    edge_mlp_kernel<<<nb_edge, 256, SMEM>>>(Ptop, Pbot, md_b0, md_wh, md_bh,
                                            srcp, dstp, acc, E);
    dec_md_kernel<<<nb_dec, 256>>>(acc, md_dw1, md_db1, md_dw2, md_db2, meshh, Nn);

    // ---- timesteps ----
    for (int t = 1; t < NTS; t++) {
        const float* fprev_in = (t == 1) ? F_initial : (const float*)Fprev;
        enc_ds_kernel<<<nb_node, 256>>>(meshh, fprev_in, F_boundary, t,
                                        ds_encw, ds_encb, henc, Nn);
        proj_ds_kernel<<<nb_node, 256>>>(henc, ds_w0, Ptop, Pbot, acc, Nn);
        edge_mlp_kernel<<<nb_edge, 256, SMEM>>>(Ptop, Pbot, ds_b0, ds_wh, ds_bh,
                                                srcp, dstp, acc, E);
        dec_ds_kernel<<<nb_dec, 256>>>(acc, ds_dw1, ds_db1, ds_dw2, ds_db2,
                                       fprev_in, dtp, Fprev, outF, outFd,
                                       t - 1, nsteps, Nn);
    }
}

// round 4
// speedup vs baseline: 1.6382x; 1.6382x over previous
#include <cuda_runtime.h>
#include <cuda_bf16.h>

#define HID   64
#define NFLD  2
#define NHH   32
#define NMF   8
#define NTS   4
#define NLAY  9          // hidden (relu,linear) layers in edge MLP
#define MAXN  10016

typedef unsigned long long u64;

// ---------------- scratch (device globals; no allocation allowed) -----------
__device__ float g_Ptop[MAXN * HID];
__device__ float g_Pbot[MAXN * HID];
__device__ float g_acc [MAXN * HID];
__device__ float g_meshh[MAXN * NHH];
__device__ float g_henc[MAXN * HID];
__device__ float g_Fprev[MAXN * NFLD];

// ---------------- packed fp32 helpers (FFMA2 path) ---------------------------
__device__ __forceinline__ u64 pack2(float x, float y) {
    u64 r;
    asm("mov.b64 %0, {%1, %2};" : "=l"(r) : "f"(x), "f"(y));
    return r;
}
__device__ __forceinline__ float2 unpack2(u64 v) {
    float2 r;
    asm("mov.b64 {%0, %1}, %2;" : "=f"(r.x), "=f"(r.y) : "l"(v));
    return r;
}
__device__ __forceinline__ void ffma2(u64& d, u64 a, u64 b) {
    asm("fma.rn.f32x2 %0, %1, %2, %0;" : "+l"(d) : "l"(a), "l"(b));
}

// A-row swizzle: rows of 128 floats, 32B chunks XOR'd by (row & 7).
// keeps 16B alignment; loads/stores must agree.
__device__ __forceinline__ int swz(int e, int f) {
    return (((e >> 3) ^ (f & 7)) << 3) | (e & 7);
}

// ---------------- per-node projection for mesh-descriptor pass --------------
__global__ void proj_md_kernel(const float* __restrict__ X,
                               const float* __restrict__ W0,
                               float* __restrict__ Ptop, float* __restrict__ Pbot,
                               float* __restrict__ acc, int Nn)
{
    int idx = blockIdx.x * blockDim.x + threadIdx.x;
    if (idx >= Nn * HID) return;
    int n = idx >> 6, j = idx & 63;
    float st = 0.f, sb = 0.f;
#pragma unroll
    for (int k = 0; k < NMF; k++) {
        float x = X[n * NMF + k];
        st = fmaf(x, W0[k * HID + j], st);
        sb = fmaf(x, W0[(NMF + k) * HID + j], sb);
    }
    Ptop[idx] = st;
    Pbot[idx] = sb;
    acc[idx]  = 0.f;
}

// ---------------- node encoder for derivative solver ------------------------
__global__ void enc_ds_kernel(const float* __restrict__ meshh,
                              const float* __restrict__ Fprev,
                              const float* __restrict__ Fb, int t,
                              const float* __restrict__ W,
                              const float* __restrict__ b,
                              float* __restrict__ henc, int Nn)
{
    int idx = blockIdx.x * blockDim.x + threadIdx.x;
    if (idx >= Nn * HID) return;
    int n = idx >> 6, j = idx & 63;
    float s = b[j];
#pragma unroll
    for (int k = 0; k < NHH; k++)
        s = fmaf(meshh[n * NHH + k], W[k * HID + j], s);
    s = fmaf(Fprev[n * NFLD + 0], W[(NHH + 0) * HID + j], s);
    s = fmaf(Fprev[n * NFLD + 1], W[(NHH + 1) * HID + j], s);
    s = fmaf(Fb[n * NTS + t],     W[(NHH + 2) * HID + j], s);
    henc[idx] = fmaxf(s, 0.f);
}

// ---------------- per-node projection for ds pass ---------------------------
__global__ void proj_ds_kernel(const float* __restrict__ Xh,
                               const float* __restrict__ W0,
                               float* __restrict__ Ptop, float* __restrict__ Pbot,
                               float* __restrict__ acc, int Nn)
{
    int idx = blockIdx.x * blockDim.x + threadIdx.x;
    if (idx >= Nn * HID) return;
    int n = idx >> 6, j = idx & 63;
    float st = 0.f, sb = 0.f;
#pragma unroll 8
    for (int k = 0; k < HID; k++) {
        float x = Xh[n * HID + k];
        st = fmaf(x, W0[k * HID + j], st);
        sb = fmaf(x, W0[(HID + k) * HID + j], sb);
    }
    Ptop[idx] = st;
    Pbot[idx] = sb;
    acc[idx]  = 0.f;
}

// ---------------- fused edge MLP + scatter -----------------------------------
// Tile: 128 edges x 64 cols, 256 threads.
// Warp grid: 4 edge-blocks x 2 col-blocks (warp = 32e x 32c).
// Lane grid:  4 e-groups  x 8 c-groups   (lane = 8e  x 4c).
// Diagonal FFMA2 packing: both operands are natural contiguous pairs; the
// anti-diagonal reuses a with a swapped w (2 MOVs per col-pair per k).
// Per k per lane: 16 FFMA2 + 3 LDS.128 + 4 MOV;  3 crossbar phases per warp.
// A rows are 32B-chunk XOR-swizzled so layer stores don't bank-conflict;
// the 8 swizzled load bases are precomputed (k&7 resolved by unroll-8).
// dyn smem: A ping/pong 2*64*128 + W ping/pong 2*64*64 floats = 98304 B.
__global__ void __launch_bounds__(256, 2)
edge_mlp_kernel(const float* __restrict__ Ptop, const float* __restrict__ Pbot,
                const float* __restrict__ b0,
                const float* __restrict__ Wh,  // (9,64,64)
                const float* __restrict__ Bh,  // (9,64)
                const int* __restrict__ src, const int* __restrict__ dst,
                float* __restrict__ acc, int E)
{
    extern __shared__ float smem[];
    float* A0  = smem;                 // [64][128] swizzled
    float* A1  = smem + 64 * 128;      // [64][128] swizzled
    float* Ws0 = smem + 2 * 64 * 128;  // [64][64]
    float* Ws1 = Ws0 + 64 * 64;        // [64][64]

    const int tid  = threadIdx.x;
    const int wid  = tid >> 5, lane = tid & 31;
    const int eb   = wid & 3,  cb   = wid >> 2;   // warp tile origin
    const int le   = lane & 3, lc   = lane >> 2;  // lane tile origin
    const int Eb   = eb * 32 + le * 8;            // 8 edges
    const int Jb   = cb * 32 + lc * 4;            // 4 cols
    const int e0   = blockIdx.x * 128;

    // ---- prologue: gather h0 = relu(Ptop[dst]+Pbot[src]+b0) into A0 --------
    for (int i = tid; i < 128 * 16; i += 256) {
        int kq = i >> 7;            // float4 group 0..15 (uniform within warp)
        int e  = i & 127;           // edge (consecutive lanes)
        int ge = e0 + e;
        float4 vt = make_float4(0.f, 0.f, 0.f, 0.f);
        float4 vb = make_float4(0.f, 0.f, 0.f, 0.f);
        if (ge < E) {
            int d = dst[ge], s = src[ge];
            vt = *(const float4*)(Ptop + d * HID + kq * 4);
            vb = *(const float4*)(Pbot + s * HID + kq * 4);
        }
        float4 bb = *(const float4*)(b0 + kq * 4);
        int k = kq * 4;
        A0[(k + 0) * 128 + swz(e, k + 0)] = fmaxf(vt.x + vb.x + bb.x, 0.f);
        A0[(k + 1) * 128 + swz(e, k + 1)] = fmaxf(vt.y + vb.y + bb.y, 0.f);
        A0[(k + 2) * 128 + swz(e, k + 2)] = fmaxf(vt.z + vb.z + bb.z, 0.f);
        A0[(k + 3) * 128 + swz(e, k + 3)] = fmaxf(vt.w + vb.w + bb.w, 0.f);
    }

    // stage layer-0 weights
    {
        const float4* Wg = (const float4*)Wh;
        for (int i = tid; i < HID * HID / 4; i += 256)
            ((float4*)Ws0)[i] = Wg[i];
    }

    // precompute the 8 swizzled A-load base offsets (selected by k&7)
    const int chunkb = Eb >> 3;
    int aoff[8];
#pragma unroll
    for (int u = 0; u < 8; u++) aoff[u] = ((chunkb ^ u) << 3);

    __syncthreads();   // A0 + Ws0 ready

    float* Acur = A0;  float* Anxt = A1;
    float* Wcur = Ws0; float* Wnxt = Ws1;

    for (int l = 0; l < NLAY; l++) {
        // stage next layer's weights into the other buffer (latency hidden)
        if (l + 1 < NLAY) {
            const float4* Wg = (const float4*)(Wh + (l + 1) * HID * HID);
            for (int i = tid; i < HID * HID / 4; i += 256)
                ((float4*)Wnxt)[i] = Wg[i];
        }

        // bias init: diagonal/anti-diagonal packed pairs
        float4 b4 = *(const float4*)(Bh + l * HID + Jb);
        const u64 m0i = pack2(b4.x, b4.y), s0i = pack2(b4.y, b4.x);
        const u64 m1i = pack2(b4.z, b4.w), s1i = pack2(b4.w, b4.z);
        u64 m0[4], s0[4], m1[4], s1[4];
#pragma unroll
        for (int p = 0; p < 4; p++) { m0[p]=m0i; s0[p]=s0i; m1[p]=m1i; s1[p]=s1i; }

#pragma unroll 8
        for (int k = 0; k < HID; k++) {
            const float* ar = Acur + (k << 7) + aoff[k & 7];
            ulonglong2 aA = *(const ulonglong2*)ar;
            ulonglong2 aB = *(const ulonglong2*)(ar + 4);
            u64 ap[4] = {aA.x, aA.y, aB.x, aB.y};

            ulonglong2 wv = *(const ulonglong2*)(Wcur + (k << 6) + Jb);
            float2 w01 = unpack2(wv.x);
            float2 w23 = unpack2(wv.y);
            u64 w01s = pack2(w01.y, w01.x);   // 2 MOVs
            u64 w23s = pack2(w23.y, w23.x);   // 2 MOVs

#pragma unroll
            for (int p = 0; p < 4; p++) {
                ffma2(m0[p], ap[p], wv.x);
                ffma2(s0[p], ap[p], w01s);
                ffma2(m1[p], ap[p], wv.y);
                ffma2(s1[p], ap[p], w23s);
            }
        }

        // unpack diagonals -> per-column edge vectors; relu except last layer
        const bool dorelu = (l != NLAY - 1);
        float c0[8], c1[8], c2[8], c3[8];
#pragma unroll
        for (int p = 0; p < 4; p++) {
            float2 vm0 = unpack2(m0[p]), vs0 = unpack2(s0[p]);
            float2 vm1 = unpack2(m1[p]), vs1 = unpack2(s1[p]);
            c0[2*p] = vm0.x; c0[2*p+1] = vs0.y;   // col Jb+0
            c1[2*p] = vs0.x; c1[2*p+1] = vm0.y;   // col Jb+1
            c2[2*p] = vm1.x; c2[2*p+1] = vs1.y;   // col Jb+2
            c3[2*p] = vs1.x; c3[2*p+1] = vm1.y;   // col Jb+3
        }
        if (dorelu) {
#pragma unroll
            for (int i = 0; i < 8; i++) {
                c0[i] = fmaxf(c0[i], 0.f); c1[i] = fmaxf(c1[i], 0.f);
                c2[i] = fmaxf(c2[i], 0.f); c3[i] = fmaxf(c3[i], 0.f);
            }
        }
#pragma unroll
        for (int c = 0; c < 4; c++) {
            const float* vv = (c == 0) ? c0 : (c == 1) ? c1 : (c == 2) ? c2 : c3;
            int j = Jb + c;
            float* dstp = Anxt + (j << 7) + (((chunkb ^ (j & 7)) << 3));
            *(float4*)(dstp    ) = make_float4(vv[0], vv[1], vv[2], vv[3]);
            *(float4*)(dstp + 4) = make_float4(vv[4], vv[5], vv[6], vv[7]);
        }

        __syncthreads();   // Anxt + Wnxt ready; all reads of Acur/Wcur done

        float* t;
        t = Acur; Acur = Anxt; Anxt = t;
        t = Wcur; Wcur = Wnxt; Wnxt = t;
    }

    // ---- epilogue: segment-sum scatter by src (scalar atomics) ----
    int e    = tid >> 1;
    int half = tid & 1;
    int ge   = e0 + e;
    if (ge < E) {
        int node = src[ge];
        float* ap = acc + node * HID + half * 32;
#pragma unroll
        for (int kk = 0; kk < 32; kk++) {
            int f = half * 32 + kk;
            atomicAdd(ap + kk, Acur[(f << 7) + swz(e, f)]);
        }
    }
}

// ---------------- node decoder (mesh descriptor) -----------------------------
__global__ void dec_md_kernel(const float* __restrict__ acc,
                              const float* __restrict__ dw1, const float* __restrict__ db1,
                              const float* __restrict__ dw2, const float* __restrict__ db2,
                              float* __restrict__ meshh, int Nn)
{
    __shared__ float t1[4][64];
    int tid = threadIdx.x;
    int q = tid >> 6, j = tid & 63;
    int n = blockIdx.x * 4 + q;
    float s = db1[j];
    if (n < Nn) {
#pragma unroll 8
        for (int k = 0; k < HID; k++)
            s = fmaf(acc[n * HID + k], dw1[k * HID + j], s);
    }
    t1[q][j] = fmaxf(s, 0.f);
    __syncthreads();
    if (tid < 128) {
        int q2 = tid >> 5, j2 = tid & 31;
        int n2 = blockIdx.x * 4 + q2;
        if (n2 < Nn) {
            float o = db2[j2];
#pragma unroll 8
            for (int k = 0; k < HID; k++)
                o = fmaf(t1[q2][k], dw2[k * NHH + j2], o);
            meshh[n2 * NHH + j2] = o;
        }
    }
}

// ---------------- node decoder (ds) + Euler step + output --------------------
__global__ void dec_ds_kernel(const float* __restrict__ acc,
                              const float* __restrict__ dw1, const float* __restrict__ db1,
                              const float* __restrict__ dw2, const float* __restrict__ db2,
                              const float* __restrict__ Fprev_in,
                              const float* __restrict__ dtp,
                              float* __restrict__ Fprev_out,
                              float* __restrict__ outF, float* __restrict__ outFd,
                              int step, int nsteps, int Nn)
{
    __shared__ float t1[4][64];
    int tid = threadIdx.x;
    int q = tid >> 6, j = tid & 63;
    int n = blockIdx.x * 4 + q;
    float s = db1[j];
    if (n < Nn) {
#pragma unroll 8
        for (int k = 0; k < HID; k++)
            s = fmaf(acc[n * HID + k], dw1[k * HID + j], s);
    }
    t1[q][j] = fmaxf(s, 0.f);
    __syncthreads();
    if (tid < 8) {
        int q2 = tid >> 1, f = tid & 1;
        int n2 = blockIdx.x * 4 + q2;
        if (n2 < Nn) {
            float o = db2[f];
#pragma unroll 8
            for (int k = 0; k < HID; k++)
                o = fmaf(t1[q2][k], dw2[k * NFLD + f], o);
            float fp = Fprev_in[n2 * NFLD + f];
            float fc = fmaf(dtp[0], o, fp);
            outF [(n2 * nsteps + step) * NFLD + f] = fc;
            outFd[(n2 * nsteps + step) * NFLD + f] = o;
            Fprev_out[n2 * NFLD + f] = fc;
        }
    }
}

// ---------------- launch ------------------------------------------------------
extern "C" void kernel_launch(void* const* d_in, const int* in_sizes, int n_in,
                              void* d_out, int out_size)
{
    const float* F_initial     = (const float*)d_in[0];
    const float* mesh_features = (const float*)d_in[1];
    const int*   edge_index    = (const int*)  d_in[2];
    const float* F_boundary    = (const float*)d_in[3];
    const float* dtp           = (const float*)d_in[4];
    const float* md_w0  = (const float*)d_in[5];
    const float* md_b0  = (const float*)d_in[6];
    const float* md_wh  = (const float*)d_in[7];
    const float* md_bh  = (const float*)d_in[8];
    const float* md_dw1 = (const float*)d_in[9];
    const float* md_db1 = (const float*)d_in[10];
    const float* md_dw2 = (const float*)d_in[11];
    const float* md_db2 = (const float*)d_in[12];
    const float* ds_encw = (const float*)d_in[13];
    const float* ds_encb = (const float*)d_in[14];
    const float* ds_w0  = (const float*)d_in[15];
    const float* ds_b0  = (const float*)d_in[16];
    const float* ds_wh  = (const float*)d_in[17];
    const float* ds_bh  = (const float*)d_in[18];
    const float* ds_dw1 = (const float*)d_in[19];
    const float* ds_db1 = (const float*)d_in[20];
    const float* ds_dw2 = (const float*)d_in[21];
    const float* ds_db2 = (const float*)d_in[22];

    int Nn = in_sizes[0] / NFLD;
    int E  = in_sizes[2] / 2;

    float *Ptop, *Pbot, *acc, *meshh, *henc, *Fprev;
    cudaGetSymbolAddress((void**)&Ptop,  g_Ptop);
    cudaGetSymbolAddress((void**)&Pbot,  g_Pbot);
    cudaGetSymbolAddress((void**)&acc,   g_acc);
    cudaGetSymbolAddress((void**)&meshh, g_meshh);
    cudaGetSymbolAddress((void**)&henc,  g_henc);
    cudaGetSymbolAddress((void**)&Fprev, g_Fprev);

    const size_t SMEM = (size_t)(2 * 64 * 128 + 2 * 64 * 64) * sizeof(float);  // 98304
    cudaFuncSetAttribute(edge_mlp_kernel,
                         cudaFuncAttributeMaxDynamicSharedMemorySize, (int)SMEM);

    const int* srcp = edge_index;
    const int* dstp = edge_index + E;

    int nb_node = (Nn * HID + 255) / 256;
    int nb_edge = (E + 127) / 128;
    int nb_dec  = (Nn + 3) / 4;
    int nsteps  = NTS - 1;

    float* outF  = (float*)d_out;
    float* outFd = outF + (size_t)out_size / 2;

    // ---- mesh descriptor pass ----
    proj_md_kernel<<<nb_node, 256>>>(mesh_features, md_w0, Ptop, Pbot, acc, Nn);
    edge_mlp_kernel<<<nb_edge, 256, SMEM>>>(Ptop, Pbot, md_b0, md_wh, md_bh,
                                            srcp, dstp, acc, E);
    dec_md_kernel<<<nb_dec, 256>>>(acc, md_dw1, md_db1, md_dw2, md_db2, meshh, Nn);

    // ---- timesteps ----
    for (int t = 1; t < NTS; t++) {
        const float* fprev_in = (t == 1) ? F_initial : (const float*)Fprev;
        enc_ds_kernel<<<nb_node, 256>>>(meshh, fprev_in, F_boundary, t,
                                        ds_encw, ds_encb, henc, Nn);
        proj_ds_kernel<<<nb_node, 256>>>(henc, ds_w0, Ptop, Pbot, acc, Nn);
        edge_mlp_kernel<<<nb_edge, 256, SMEM>>>(Ptop, Pbot, ds_b0, ds_wh, ds_bh,
                                                srcp, dstp, acc, E);
        dec_ds_kernel<<<nb_dec, 256>>>(acc, ds_dw1, ds_db1, ds_dw2, ds_db2,
                                       fprev_in, dtp, Fprev, outF, outFd,
                                       t - 1, nsteps, Nn);
    }
}

// round 5
// speedup vs baseline: 1.6947x; 1.0345x over previous
#include <cuda_runtime.h>
#include <cuda_bf16.h>

#define HID   64
#define NFLD  2
#define NHH   32
#define NMF   8
#define NTS   4
#define NLAY  9          // hidden (relu,linear) layers in edge MLP
#define MAXN  10016

typedef unsigned long long u64;

// ---------------- scratch (device globals; no allocation allowed) -----------
__device__ float g_Ptop[MAXN * HID];
__device__ float g_Pbot[MAXN * HID];
__device__ float g_acc [MAXN * HID];
__device__ float g_meshh[MAXN * NHH];
__device__ float g_henc[MAXN * HID];
__device__ float g_Fprev[MAXN * NFLD];

// ---------------- packed fp32 helpers (FFMA2 path) ---------------------------
__device__ __forceinline__ u64 pack2(float x, float y) {
    u64 r;
    asm("mov.b64 %0, {%1, %2};" : "=l"(r) : "f"(x), "f"(y));
    return r;
}
__device__ __forceinline__ u64 dup2(float x) {
    u64 r;
    asm("mov.b64 %0, {%1, %1};" : "=l"(r) : "f"(x));
    return r;
}
__device__ __forceinline__ float2 unpack2(u64 v) {
    float2 r;
    asm("mov.b64 {%0, %1}, %2;" : "=f"(r.x), "=f"(r.y) : "l"(v));
    return r;
}
__device__ __forceinline__ void ffma2(u64& d, u64 a, u64 b) {
    asm("fma.rn.f32x2 %0, %1, %2, %0;" : "+l"(d) : "l"(a), "l"(b));
}

// ---------------- per-node projection for mesh-descriptor pass --------------
__global__ void proj_md_kernel(const float* __restrict__ X,
                               const float* __restrict__ W0,
                               float* __restrict__ Ptop, float* __restrict__ Pbot,
                               float* __restrict__ acc, int Nn)
{
    int idx = blockIdx.x * blockDim.x + threadIdx.x;
    if (idx >= Nn * HID) return;
    int n = idx >> 6, j = idx & 63;
    float st = 0.f, sb = 0.f;
#pragma unroll
    for (int k = 0; k < NMF; k++) {
        float x = X[n * NMF + k];
        st = fmaf(x, W0[k * HID + j], st);
        sb = fmaf(x, W0[(NMF + k) * HID + j], sb);
    }
    Ptop[idx] = st;
    Pbot[idx] = sb;
    acc[idx]  = 0.f;
}

// ---------------- node encoder for derivative solver ------------------------
__global__ void enc_ds_kernel(const float* __restrict__ meshh,
                              const float* __restrict__ Fprev,
                              const float* __restrict__ Fb, int t,
                              const float* __restrict__ W,
                              const float* __restrict__ b,
                              float* __restrict__ henc, int Nn)
{
    int idx = blockIdx.x * blockDim.x + threadIdx.x;
    if (idx >= Nn * HID) return;
    int n = idx >> 6, j = idx & 63;
    float s = b[j];
#pragma unroll
    for (int k = 0; k < NHH; k++)
        s = fmaf(meshh[n * NHH + k], W[k * HID + j], s);
    s = fmaf(Fprev[n * NFLD + 0], W[(NHH + 0) * HID + j], s);
    s = fmaf(Fprev[n * NFLD + 1], W[(NHH + 1) * HID + j], s);
    s = fmaf(Fb[n * NTS + t],     W[(NHH + 2) * HID + j], s);
    henc[idx] = fmaxf(s, 0.f);
}

// ---------------- per-node projection for ds pass ---------------------------
__global__ void proj_ds_kernel(const float* __restrict__ Xh,
                               const float* __restrict__ W0,
                               float* __restrict__ Ptop, float* __restrict__ Pbot,
                               float* __restrict__ acc, int Nn)
{
    int idx = blockIdx.x * blockDim.x + threadIdx.x;
    if (idx >= Nn * HID) return;
    int n = idx >> 6, j = idx & 63;
    float st = 0.f, sb = 0.f;
#pragma unroll 8
    for (int k = 0; k < HID; k++) {
        float x = Xh[n * HID + k];
        st = fmaf(x, W0[k * HID + j], st);
        sb = fmaf(x, W0[(HID + k) * HID + j], sb);
    }
    Ptop[idx] = st;
    Pbot[idx] = sb;
    acc[idx]  = 0.f;
}

// ---------------- persistent fused edge MLP + scatter ------------------------
// 148 persistent CTAs, 1 CTA/SM, 256 threads. Each CTA loops over 128-edge
// tiles (static stride schedule). ALL 9 layers' weights (144KB) staged into
// smem ONCE and kept resident; A ping/pong 2x32KB. Inner loop = R2's proven
// FFMA2 kernel (thread tile 4 edges x 8 cols, col-pair packing, W broadcast).
// One __syncthreads per layer; epilogue atomics overlap next tile's gather.
// dyn smem: 2*64*128 + 9*64*64 floats = 212992 B.
__global__ void __launch_bounds__(256, 1)
edge_mlp_kernel(const float* __restrict__ Ptop, const float* __restrict__ Pbot,
                const float* __restrict__ b0,
                const float* __restrict__ Wh,  // (9,64,64)
                const float* __restrict__ Bh,  // (9,64)
                const int* __restrict__ src, const int* __restrict__ dst,
                float* __restrict__ acc, int E)
{
    extern __shared__ float smem[];
    float* A0 = smem;                 // [64][128]
    float* A1 = smem + 64 * 128;      // [64][128]
    float* Ws = smem + 2 * 64 * 128;  // [9][64][64] resident

    const int tid = threadIdx.x;
    const int te  = tid & 31;         // edge-quad index (4 edges each)
    const int tj  = tid >> 5;         // column-octet index (8 cols each)

    // ---- stage ALL layer weights once (resident for the whole kernel) ----
    {
        const float4* Wg = (const float4*)Wh;
        float4*       Wd = (float4*)Ws;
        for (int i = tid; i < NLAY * HID * HID / 4; i += 256)
            Wd[i] = Wg[i];
    }

    const int ntiles = (E + 127) >> 7;

    for (int tile = blockIdx.x; tile < ntiles; tile += gridDim.x) {
        const int e0 = tile << 7;

        // ---- prologue: gather h0 = relu(Ptop[dst]+Pbot[src]+b0) into A0 ----
        // (overlaps the previous tile's epilogue atomics: disjoint buffers)
        for (int i = tid; i < 128 * 16; i += 256) {
            int kq = i >> 7;            // float4 group (uniform within warp)
            int e  = i & 127;           // edge (consecutive lanes)
            int ge = e0 + e;
            float4 vt = make_float4(0.f, 0.f, 0.f, 0.f);
            float4 vb = make_float4(0.f, 0.f, 0.f, 0.f);
            if (ge < E) {
                int d = dst[ge], s = src[ge];
                vt = *(const float4*)(Ptop + d * HID + kq * 4);
                vb = *(const float4*)(Pbot + s * HID + kq * 4);
            }
            float4 bb = *(const float4*)(b0 + kq * 4);
            int k = kq * 4;
            A0[(k + 0) * 128 + e] = fmaxf(vt.x + vb.x + bb.x, 0.f);
            A0[(k + 1) * 128 + e] = fmaxf(vt.y + vb.y + bb.y, 0.f);
            A0[(k + 2) * 128 + e] = fmaxf(vt.z + vb.z + bb.z, 0.f);
            A0[(k + 3) * 128 + e] = fmaxf(vt.w + vb.w + bb.w, 0.f);
        }
        __syncthreads();   // A0 ready (also: W staging done / epilogue done)

        float* Acur = A0;
        float* Anxt = A1;

        for (int l = 0; l < NLAY; l++) {
            const float* Wl = Ws + l * HID * HID;

            // bias init: packed (b_j, b_j+1) pairs, replicated over 4 edges
            u64 acc2[4][4];
#pragma unroll
            for (int jp = 0; jp < 4; jp++) {
                float2 b2 = *(const float2*)(Bh + l * HID + (tj << 3) + jp * 2);
                u64 bp = pack2(b2.x, b2.y);
#pragma unroll
                for (int q = 0; q < 4; q++) acc2[q][jp] = bp;
            }

#pragma unroll 8
            for (int k = 0; k < HID; k++) {
                float4 a4 = *(const float4*)(Acur + (k << 7) + (te << 2));
                u64 ap[4];
                ap[0] = dup2(a4.x); ap[1] = dup2(a4.y);
                ap[2] = dup2(a4.z); ap[3] = dup2(a4.w);
                ulonglong2 w01 = *(const ulonglong2*)(Wl + (k << 6) + (tj << 3));
                ulonglong2 w23 = *(const ulonglong2*)(Wl + (k << 6) + (tj << 3) + 4);
                u64 wp[4] = {w01.x, w01.y, w23.x, w23.y};
#pragma unroll
                for (int q = 0; q < 4; q++)
#pragma unroll
                    for (int jp = 0; jp < 4; jp++)
                        ffma2(acc2[q][jp], ap[q], wp[jp]);
            }

            // write next activations [j][e]; relu except last layer
            const bool dorelu = (l != NLAY - 1);
#pragma unroll
            for (int jp = 0; jp < 4; jp++) {
                float2 v0 = unpack2(acc2[0][jp]);
                float2 v1 = unpack2(acc2[1][jp]);
                float2 v2 = unpack2(acc2[2][jp]);
                float2 v3 = unpack2(acc2[3][jp]);
                float4 c0 = make_float4(v0.x, v1.x, v2.x, v3.x);
                float4 c1 = make_float4(v0.y, v1.y, v2.y, v3.y);
                if (dorelu) {
                    c0.x = fmaxf(c0.x, 0.f); c0.y = fmaxf(c0.y, 0.f);
                    c0.z = fmaxf(c0.z, 0.f); c0.w = fmaxf(c0.w, 0.f);
                    c1.x = fmaxf(c1.x, 0.f); c1.y = fmaxf(c1.y, 0.f);
                    c1.z = fmaxf(c1.z, 0.f); c1.w = fmaxf(c1.w, 0.f);
                }
                int j0 = (tj << 3) + jp * 2;
                *(float4*)(Anxt + ((j0 + 0) << 7) + (te << 2)) = c0;
                *(float4*)(Anxt + ((j0 + 1) << 7) + (te << 2)) = c1;
            }

            __syncthreads();   // Anxt complete; all reads of Acur done

            float* t = Acur; Acur = Anxt; Anxt = t;
        }

        // ---- epilogue: segment-sum scatter by src ----
        // (final activations live in Acur = A1 for NLAY=9; next gather
        //  writes A0, so this overlaps with the next tile's prologue)
        int e    = tid >> 1;
        int half = tid & 1;
        int ge   = e0 + e;
        if (ge < E) {
            int node = src[ge];
            float* ap = acc + node * HID + half * 32;
#pragma unroll
            for (int kk = 0; kk < 32; kk++)
                atomicAdd(ap + kk, Acur[((half * 32 + kk) << 7) + e]);
        }
    }
}

// ---------------- node decoder (mesh descriptor) -----------------------------
__global__ void dec_md_kernel(const float* __restrict__ acc,
                              const float* __restrict__ dw1, const float* __restrict__ db1,
                              const float* __restrict__ dw2, const float* __restrict__ db2,
                              float* __restrict__ meshh, int Nn)
{
    __shared__ float t1[4][64];
    int tid = threadIdx.x;
    int q = tid >> 6, j = tid & 63;
    int n = blockIdx.x * 4 + q;
    float s = db1[j];
    if (n < Nn) {
#pragma unroll 8
        for (int k = 0; k < HID; k++)
            s = fmaf(acc[n * HID + k], dw1[k * HID + j], s);
    }
    t1[q][j] = fmaxf(s, 0.f);
    __syncthreads();
    if (tid < 128) {
        int q2 = tid >> 5, j2 = tid & 31;
        int n2 = blockIdx.x * 4 + q2;
        if (n2 < Nn) {
            float o = db2[j2];
#pragma unroll 8
            for (int k = 0; k < HID; k++)
                o = fmaf(t1[q2][k], dw2[k * NHH + j2], o);
            meshh[n2 * NHH + j2] = o;
        }
    }
}

// ---------------- node decoder (ds) + Euler step + output --------------------
__global__ void dec_ds_kernel(const float* __restrict__ acc,
                              const float* __restrict__ dw1, const float* __restrict__ db1,
                              const float* __restrict__ dw2, const float* __restrict__ db2,
                              const float* __restrict__ Fprev_in,
                              const float* __restrict__ dtp,
                              float* __restrict__ Fprev_out,
                              float* __restrict__ outF, float* __restrict__ outFd,
                              int step, int nsteps, int Nn)
{
    __shared__ float t1[4][64];
    int tid = threadIdx.x;
    int q = tid >> 6, j = tid & 63;
    int n = blockIdx.x * 4 + q;
    float s = db1[j];
    if (n < Nn) {
#pragma unroll 8
        for (int k = 0; k < HID; k++)
            s = fmaf(acc[n * HID + k], dw1[k * HID + j], s);
    }
    t1[q][j] = fmaxf(s, 0.f);
    __syncthreads();
    if (tid < 8) {
        int q2 = tid >> 1, f = tid & 1;
        int n2 = blockIdx.x * 4 + q2;
        if (n2 < Nn) {
            float o = db2[f];
#pragma unroll 8
            for (int k = 0; k < HID; k++)
                o = fmaf(t1[q2][k], dw2[k * NFLD + f], o);
            float fp = Fprev_in[n2 * NFLD + f];
            float fc = fmaf(dtp[0], o, fp);
            outF [(n2 * nsteps + step) * NFLD + f] = fc;
            outFd[(n2 * nsteps + step) * NFLD + f] = o;
            Fprev_out[n2 * NFLD + f] = fc;
        }
    }
}

// ---------------- launch ------------------------------------------------------
extern "C" void kernel_launch(void* const* d_in, const int* in_sizes, int n_in,
                              void* d_out, int out_size)
{
    const float* F_initial     = (const float*)d_in[0];
    const float* mesh_features = (const float*)d_in[1];
    const int*   edge_index    = (const int*)  d_in[2];
    const float* F_boundary    = (const float*)d_in[3];
    const float* dtp           = (const float*)d_in[4];
    const float* md_w0  = (const float*)d_in[5];
    const float* md_b0  = (const float*)d_in[6];
    const float* md_wh  = (const float*)d_in[7];
    const float* md_bh  = (const float*)d_in[8];
    const float* md_dw1 = (const float*)d_in[9];
    const float* md_db1 = (const float*)d_in[10];
    const float* md_dw2 = (const float*)d_in[11];
    const float* md_db2 = (const float*)d_in[12];
    const float* ds_encw = (const float*)d_in[13];
    const float* ds_encb = (const float*)d_in[14];
    const float* ds_w0  = (const float*)d_in[15];
    const float* ds_b0  = (const float*)d_in[16];
    const float* ds_wh  = (const float*)d_in[17];
    const float* ds_bh  = (const float*)d_in[18];
    const float* ds_dw1 = (const float*)d_in[19];
    const float* ds_db1 = (const float*)d_in[20];
    const float* ds_dw2 = (const float*)d_in[21];
    const float* ds_db2 = (const float*)d_in[22];

    int Nn = in_sizes[0] / NFLD;
    int E  = in_sizes[2] / 2;

    float *Ptop, *Pbot, *acc, *meshh, *henc, *Fprev;
    cudaGetSymbolAddress((void**)&Ptop,  g_Ptop);
    cudaGetSymbolAddress((void**)&Pbot,  g_Pbot);
    cudaGetSymbolAddress((void**)&acc,   g_acc);
    cudaGetSymbolAddress((void**)&meshh, g_meshh);
    cudaGetSymbolAddress((void**)&henc,  g_henc);
    cudaGetSymbolAddress((void**)&Fprev, g_Fprev);

    const size_t SMEM = (size_t)(2 * 64 * 128 + NLAY * 64 * 64) * sizeof(float); // 212992
    cudaFuncSetAttribute(edge_mlp_kernel,
                         cudaFuncAttributeMaxDynamicSharedMemorySize, (int)SMEM);

    const int* srcp = edge_index;
    const int* dstp = edge_index + E;

    int nb_node = (Nn * HID + 255) / 256;
    int nb_dec  = (Nn + 3) / 4;
    int nsteps  = NTS - 1;
    int ntiles  = (E + 127) / 128;
    int nb_edge = ntiles < 148 ? ntiles : 148;   // persistent: 1 CTA/SM

    float* outF  = (float*)d_out;
    float* outFd = outF + (size_t)out_size / 2;

    // ---- mesh descriptor pass ----
    proj_md_kernel<<<nb_node, 256>>>(mesh_features, md_w0, Ptop, Pbot, acc, Nn);
    edge_mlp_kernel<<<nb_edge, 256, SMEM>>>(Ptop, Pbot, md_b0, md_wh, md_bh,
                                            srcp, dstp, acc, E);
    dec_md_kernel<<<nb_dec, 256>>>(acc, md_dw1, md_db1, md_dw2, md_db2, meshh, Nn);

    // ---- timesteps ----
    for (int t = 1; t < NTS; t++) {
        const float* fprev_in = (t == 1) ? F_initial : (const float*)Fprev;
        enc_ds_kernel<<<nb_node, 256>>>(meshh, fprev_in, F_boundary, t,
                                        ds_encw, ds_encb, henc, Nn);
        proj_ds_kernel<<<nb_node, 256>>>(henc, ds_w0, Ptop, Pbot, acc, Nn);
        edge_mlp_kernel<<<nb_edge, 256, SMEM>>>(Ptop, Pbot, ds_b0, ds_wh, ds_bh,
                                                srcp, dstp, acc, E);
        dec_ds_kernel<<<nb_dec, 256>>>(acc, ds_dw1, ds_db1, ds_dw2, ds_db2,
                                       fprev_in, dtp, Fprev, outF, outFd,
                                       t - 1, nsteps, Nn);
    }
}

// round 6
// speedup vs baseline: 1.7733x; 1.0463x over previous
#include <cuda_runtime.h>
#include <cuda_bf16.h>

#define HID   64
#define NFLD  2
#define NHH   32
#define NMF   8
#define NTS   4
#define NLAY  9          // hidden (relu,linear) layers in edge MLP
#define MAXN  10016

typedef unsigned long long u64;

// ---------------- scratch (device globals; no allocation allowed) -----------
__device__ float g_Ptop[MAXN * HID];
__device__ float g_Pbot[MAXN * HID];
__device__ float g_acc [MAXN * HID];
__device__ float g_meshh[MAXN * NHH];
__device__ float g_Fprev[MAXN * NFLD];
__device__ int   g_ctr;

// ---------------- packed fp32 helpers (FFMA2 path) ---------------------------
__device__ __forceinline__ u64 pack2(float x, float y) {
    u64 r;
    asm("mov.b64 %0, {%1, %2};" : "=l"(r) : "f"(x), "f"(y));
    return r;
}
__device__ __forceinline__ u64 dup2(float x) {
    u64 r;
    asm("mov.b64 %0, {%1, %1};" : "=l"(r) : "f"(x));
    return r;
}
__device__ __forceinline__ float2 unpack2(u64 v) {
    float2 r;
    asm("mov.b64 {%0, %1}, %2;" : "=f"(r.x), "=f"(r.y) : "l"(v));
    return r;
}
__device__ __forceinline__ void ffma2(u64& d, u64 a, u64 b) {
    asm("fma.rn.f32x2 %0, %1, %2, %0;" : "+l"(d) : "l"(a), "l"(b));
}

// ---------------- per-node projection for mesh-descriptor pass --------------
__global__ void proj_md_kernel(const float* __restrict__ X,
                               const float* __restrict__ W0,
                               float* __restrict__ Ptop, float* __restrict__ Pbot,
                               float* __restrict__ acc, int Nn, int ctr0)
{
    int idx = blockIdx.x * blockDim.x + threadIdx.x;
    if (idx == 0) g_ctr = ctr0;          // reset dynamic-tile counter
    if (idx >= Nn * HID) return;
    int n = idx >> 6, j = idx & 63;
    float st = 0.f, sb = 0.f;
#pragma unroll
    for (int k = 0; k < NMF; k++) {
        float x = X[n * NMF + k];
        st = fmaf(x, W0[k * HID + j], st);
        sb = fmaf(x, W0[(NMF + k) * HID + j], sb);
    }
    Ptop[idx] = st;
    Pbot[idx] = sb;
    acc[idx]  = 0.f;
}

// ---------------- fused node encoder + projection (ds pass) ------------------
// henc = relu([meshh, F_prev, F_b] @ encW + encb) staged in SMEM only;
// Ptop = henc @ W0[0:64,:],  Pbot = henc @ W0[64:128,:];  acc zeroed.
__global__ void encproj_ds_kernel(const float* __restrict__ meshh,
                                  const float* __restrict__ Fprev,
                                  const float* __restrict__ Fb, int t,
                                  const float* __restrict__ encW,
                                  const float* __restrict__ encb,
                                  const float* __restrict__ W0,
                                  float* __restrict__ Ptop, float* __restrict__ Pbot,
                                  float* __restrict__ acc, int Nn, int ctr0)
{
    __shared__ float sh[4][64];
    int tid = threadIdx.x;
    if (blockIdx.x == 0 && tid == 0) g_ctr = ctr0;   // reset tile counter
    int q = tid >> 6, j = tid & 63;
    int n = blockIdx.x * 4 + q;
    float s = encb[j];
    if (n < Nn) {
#pragma unroll
        for (int k = 0; k < NHH; k++)
            s = fmaf(meshh[n * NHH + k], encW[k * HID + j], s);
        s = fmaf(Fprev[n * NFLD + 0], encW[(NHH + 0) * HID + j], s);
        s = fmaf(Fprev[n * NFLD + 1], encW[(NHH + 1) * HID + j], s);
        s = fmaf(Fb[n * NTS + t],     encW[(NHH + 2) * HID + j], s);
    }
    sh[q][j] = fmaxf(s, 0.f);
    __syncthreads();
    if (n < Nn) {
        float st = 0.f, sb = 0.f;
#pragma unroll 8
        for (int k = 0; k < HID; k++) {
            float x = sh[q][k];
            st = fmaf(x, W0[k * HID + j], st);
            sb = fmaf(x, W0[(HID + k) * HID + j], sb);
        }
        int idx = n * HID + j;
        Ptop[idx] = st;
        Pbot[idx] = sb;
        acc[idx]  = 0.f;
    }
}

// ---------------- persistent fused edge MLP + scatter ------------------------
// 296 persistent CTAs (2/SM), 256 threads, 128-edge tiles via dynamic counter.
// Inner loop identical to R2 (thread tile 4 edges x 8 cols, col-pair FFMA2,
// W broadcast). ONE __syncthreads per layer: A and W both ping-ponged, so
// {read Acur/Wcur -> store Anxt -> STS Wnxt -> sync -> swap} is sufficient.
// W prefetch wraps (l+1)%NLAY so layer-0 is restaged during layer-8 compute.
// Epilogue atomics + next gather overlap compute via buffer disjointness.
// dyn smem: A ping/pong 2*64*128 + W ping/pong 2*64*64 floats = 98304 B.
__global__ void __launch_bounds__(256, 2)
edge_mlp_kernel(const float* __restrict__ Ptop, const float* __restrict__ Pbot,
                const float* __restrict__ b0,
                const float* __restrict__ Wh,  // (9,64,64)
                const float* __restrict__ Bh,  // (9,64)
                const int* __restrict__ src, const int* __restrict__ dst,
                float* __restrict__ acc, int E)
{
    extern __shared__ float smem[];
    float* A0  = smem;                 // [64][128]
    float* A1  = smem + 64 * 128;      // [64][128]
    float* Ws0 = smem + 2 * 64 * 128;  // [64][64]
    float* Ws1 = Ws0 + 64 * 64;        // [64][64]
    __shared__ int s_next;

    const int tid = threadIdx.x;
    const int te  = tid & 31;          // edge-quad index (4 edges each)
    const int tj  = tid >> 5;          // column-octet index (8 cols each)
    const int ntiles = (E + 127) >> 7;

    // stage layer-0 weights into Ws0
    {
        const float4* Wg = (const float4*)Wh;
        for (int i = tid; i < HID * HID / 4; i += 256)
            ((float4*)Ws0)[i] = Wg[i];
    }

    float* Acur = A0;  float* Anxt = A1;
    float* Wcur = Ws0; float* Wnxt = Ws1;

    int tile = blockIdx.x;
    if (tile >= ntiles) return;

    // ---- first gather into Acur ----
    {
        const int e0 = tile << 7;
        for (int i = tid; i < 128 * 16; i += 256) {
            int kq = i >> 7, e = i & 127;
            int ge = e0 + e;
            float4 vt = make_float4(0.f, 0.f, 0.f, 0.f);
            float4 vb = make_float4(0.f, 0.f, 0.f, 0.f);
            if (ge < E) {
                int d = dst[ge], s = src[ge];
                vt = *(const float4*)(Ptop + d * HID + kq * 4);
                vb = *(const float4*)(Pbot + s * HID + kq * 4);
            }
            float4 bb = *(const float4*)(b0 + kq * 4);
            int k = kq * 4;
            Acur[(k + 0) * 128 + e] = fmaxf(vt.x + vb.x + bb.x, 0.f);
            Acur[(k + 1) * 128 + e] = fmaxf(vt.y + vb.y + bb.y, 0.f);
            Acur[(k + 2) * 128 + e] = fmaxf(vt.z + vb.z + bb.z, 0.f);
            Acur[(k + 3) * 128 + e] = fmaxf(vt.w + vb.w + bb.w, 0.f);
        }
    }
    if (tid == 0) s_next = atomicAdd(&g_ctr, 1);
    __syncthreads();   // Acur + Ws0 + s_next ready

    for (;;) {
        const int e0 = tile << 7;

        // ---- 9 layers, one sync each ----
        for (int l = 0; l < NLAY; l++) {
            // prefetch next layer's weights ((l+1) mod 9 -> layer0 for next tile)
            int lnxt = (l + 1 == NLAY) ? 0 : l + 1;
            float4 wreg[4];
            {
                const float4* Wg = (const float4*)(Wh + lnxt * HID * HID);
#pragma unroll
                for (int i = 0; i < 4; i++) wreg[i] = Wg[tid * 4 + i];
            }

            // bias init: packed (b_j, b_j+1) pairs, replicated over 4 edges
            u64 acc2[4][4];
#pragma unroll
            for (int jp = 0; jp < 4; jp++) {
                float2 b2 = *(const float2*)(Bh + l * HID + (tj << 3) + jp * 2);
                u64 bp = pack2(b2.x, b2.y);
#pragma unroll
                for (int q = 0; q < 4; q++) acc2[q][jp] = bp;
            }

#pragma unroll 8
            for (int k = 0; k < HID; k++) {
                float4 a4 = *(const float4*)(Acur + (k << 7) + (te << 2));
                u64 ap[4];
                ap[0] = dup2(a4.x); ap[1] = dup2(a4.y);
                ap[2] = dup2(a4.z); ap[3] = dup2(a4.w);
                ulonglong2 w01 = *(const ulonglong2*)(Wcur + (k << 6) + (tj << 3));
                ulonglong2 w23 = *(const ulonglong2*)(Wcur + (k << 6) + (tj << 3) + 4);
                u64 wp[4] = {w01.x, w01.y, w23.x, w23.y};
#pragma unroll
                for (int q = 0; q < 4; q++)
#pragma unroll
                    for (int jp = 0; jp < 4; jp++)
                        ffma2(acc2[q][jp], ap[q], wp[jp]);
            }

            // write next activations [j][e]; relu except last layer
            const bool dorelu = (l != NLAY - 1);
#pragma unroll
            for (int jp = 0; jp < 4; jp++) {
                float2 v0 = unpack2(acc2[0][jp]);
                float2 v1 = unpack2(acc2[1][jp]);
                float2 v2 = unpack2(acc2[2][jp]);
                float2 v3 = unpack2(acc2[3][jp]);
                float4 c0 = make_float4(v0.x, v1.x, v2.x, v3.x);
                float4 c1 = make_float4(v0.y, v1.y, v2.y, v3.y);
                if (dorelu) {
                    c0.x = fmaxf(c0.x, 0.f); c0.y = fmaxf(c0.y, 0.f);
                    c0.z = fmaxf(c0.z, 0.f); c0.w = fmaxf(c0.w, 0.f);
                    c1.x = fmaxf(c1.x, 0.f); c1.y = fmaxf(c1.y, 0.f);
                    c1.z = fmaxf(c1.z, 0.f); c1.w = fmaxf(c1.w, 0.f);
                }
                int j0 = (tj << 3) + jp * 2;
                *(float4*)(Anxt + ((j0 + 0) << 7) + (te << 2)) = c0;
                *(float4*)(Anxt + ((j0 + 1) << 7) + (te << 2)) = c1;
            }

            // stage prefetched weights into the other W buffer
            {
                float4* Wd = (float4*)Wnxt;
#pragma unroll
                for (int i = 0; i < 4; i++) Wd[tid * 4 + i] = wreg[i];
            }

            __syncthreads();   // the single per-layer barrier

            float* t;
            t = Acur; Acur = Anxt; Anxt = t;
            t = Wcur; Wcur = Wnxt; Wnxt = t;
        }

        // ---- epilogue: segment-sum scatter by src (reads Acur) ----
        {
            int e    = tid >> 1;
            int half = tid & 1;
            int ge   = e0 + e;
            if (ge < E) {
                int node = src[ge];
                float* ap = acc + node * HID + half * 32;
#pragma unroll
                for (int kk = 0; kk < 32; kk++)
                    atomicAdd(ap + kk, Acur[((half * 32 + kk) << 7) + e]);
            }
        }

        tile = s_next;
        if (tile >= ntiles) break;

        // ---- gather next tile into Anxt (free buffer); overlaps epilogue ----
        {
            const int ne0 = tile << 7;
            for (int i = tid; i < 128 * 16; i += 256) {
                int kq = i >> 7, e = i & 127;
                int ge = ne0 + e;
                float4 vt = make_float4(0.f, 0.f, 0.f, 0.f);
                float4 vb = make_float4(0.f, 0.f, 0.f, 0.f);
                if (ge < E) {
                    int d = dst[ge], s = src[ge];
                    vt = *(const float4*)(Ptop + d * HID + kq * 4);
                    vb = *(const float4*)(Pbot + s * HID + kq * 4);
                }
                float4 bb = *(const float4*)(b0 + kq * 4);
                int k = kq * 4;
                Anxt[(k + 0) * 128 + e] = fmaxf(vt.x + vb.x + bb.x, 0.f);
                Anxt[(k + 1) * 128 + e] = fmaxf(vt.y + vb.y + bb.y, 0.f);
                Anxt[(k + 2) * 128 + e] = fmaxf(vt.z + vb.z + bb.z, 0.f);
                Anxt[(k + 3) * 128 + e] = fmaxf(vt.w + vb.w + bb.w, 0.f);
            }
        }
        if (tid == 0) s_next = atomicAdd(&g_ctr, 1);
        __syncthreads();   // gather + epilogue reads of Acur complete; s_next ready

        // swap so the layer loop reads the freshly gathered buffer
        float* t = Acur; Acur = Anxt; Anxt = t;
    }
}

// ---------------- node decoder (mesh descriptor) -----------------------------
__global__ void dec_md_kernel(const float* __restrict__ acc,
                              const float* __restrict__ dw1, const float* __restrict__ db1,
                              const float* __restrict__ dw2, const float* __restrict__ db2,
                              float* __restrict__ meshh, int Nn)
{
    __shared__ float t1[4][64];
    int tid = threadIdx.x;
    int q = tid >> 6, j = tid & 63;
    int n = blockIdx.x * 4 + q;
    float s = db1[j];
    if (n < Nn) {
#pragma unroll 8
        for (int k = 0; k < HID; k++)
            s = fmaf(acc[n * HID + k], dw1[k * HID + j], s);
    }
    t1[q][j] = fmaxf(s, 0.f);
    __syncthreads();
    if (tid < 128) {
        int q2 = tid >> 5, j2 = tid & 31;
        int n2 = blockIdx.x * 4 + q2;
        if (n2 < Nn) {
            float o = db2[j2];
#pragma unroll 8
            for (int k = 0; k < HID; k++)
                o = fmaf(t1[q2][k], dw2[k * NHH + j2], o);
            meshh[n2 * NHH + j2] = o;
        }
    }
}

// ---------------- node decoder (ds) + Euler step + output --------------------
__global__ void dec_ds_kernel(const float* __restrict__ acc,
                              const float* __restrict__ dw1, const float* __restrict__ db1,
                              const float* __restrict__ dw2, const float* __restrict__ db2,
                              const float* __restrict__ Fprev_in,
                              const float* __restrict__ dtp,
                              float* __restrict__ Fprev_out,
                              float* __restrict__ outF, float* __restrict__ outFd,
                              int step, int nsteps, int Nn)
{
    __shared__ float t1[4][64];
    int tid = threadIdx.x;
    int q = tid >> 6, j = tid & 63;
    int n = blockIdx.x * 4 + q;
    float s = db1[j];
    if (n < Nn) {
#pragma unroll 8
        for (int k = 0; k < HID; k++)
            s = fmaf(acc[n * HID + k], dw1[k * HID + j], s);
    }
    t1[q][j] = fmaxf(s, 0.f);
    __syncthreads();
    if (tid < 8) {
        int q2 = tid >> 1, f = tid & 1;
        int n2 = blockIdx.x * 4 + q2;
        if (n2 < Nn) {
            float o = db2[f];
#pragma unroll 8
            for (int k = 0; k < HID; k++)
                o = fmaf(t1[q2][k], dw2[k * NFLD + f], o);
            float fp = Fprev_in[n2 * NFLD + f];
            float fc = fmaf(dtp[0], o, fp);
            outF [(n2 * nsteps + step) * NFLD + f] = fc;
            outFd[(n2 * nsteps + step) * NFLD + f] = o;
            Fprev_out[n2 * NFLD + f] = fc;
        }
    }
}

// ---------------- launch ------------------------------------------------------
extern "C" void kernel_launch(void* const* d_in, const int* in_sizes, int n_in,
                              void* d_out, int out_size)
{
    const float* F_initial     = (const float*)d_in[0];
    const float* mesh_features = (const float*)d_in[1];
    const int*   edge_index    = (const int*)  d_in[2];
    const float* F_boundary    = (const float*)d_in[3];
    const float* dtp           = (const float*)d_in[4];
    const float* md_w0  = (const float*)d_in[5];
    const float* md_b0  = (const float*)d_in[6];
    const float* md_wh  = (const float*)d_in[7];
    const float* md_bh  = (const float*)d_in[8];
    const float* md_dw1 = (const float*)d_in[9];
    const float* md_db1 = (const float*)d_in[10];
    const float* md_dw2 = (const float*)d_in[11];
    const float* md_db2 = (const float*)d_in[12];
    const float* ds_encw = (const float*)d_in[13];
    const float* ds_encb = (const float*)d_in[14];
    const float* ds_w0  = (const float*)d_in[15];
    const float* ds_b0  = (const float*)d_in[16];
    const float* ds_wh  = (const float*)d_in[17];
    const float* ds_bh  = (const float*)d_in[18];
    const float* ds_dw1 = (const float*)d_in[19];
    const float* ds_db1 = (const float*)d_in[20];
    const float* ds_dw2 = (const float*)d_in[21];
    const float* ds_db2 = (const float*)d_in[22];

    int Nn = in_sizes[0] / NFLD;
    int E  = in_sizes[2] / 2;

    float *Ptop, *Pbot, *acc, *meshh, *Fprev;
    cudaGetSymbolAddress((void**)&Ptop,  g_Ptop);
    cudaGetSymbolAddress((void**)&Pbot,  g_Pbot);
    cudaGetSymbolAddress((void**)&acc,   g_acc);
    cudaGetSymbolAddress((void**)&meshh, g_meshh);
    cudaGetSymbolAddress((void**)&Fprev, g_Fprev);

    const size_t SMEM = (size_t)(2 * 64 * 128 + 2 * 64 * 64) * sizeof(float);  // 98304
    cudaFuncSetAttribute(edge_mlp_kernel,
                         cudaFuncAttributeMaxDynamicSharedMemorySize, (int)SMEM);

    const int* srcp = edge_index;
    const int* dstp = edge_index + E;

    int nb_node = (Nn * HID + 255) / 256;
    int nb_dec  = (Nn + 3) / 4;
    int nsteps  = NTS - 1;
    int ntiles  = (E + 127) / 128;
    int nb_edge = ntiles < 296 ? ntiles : 296;   // persistent, 2 CTA/SM

    float* outF  = (float*)d_out;
    float* outFd = outF + (size_t)out_size / 2;

    // ---- mesh descriptor pass ----
    proj_md_kernel<<<nb_node, 256>>>(mesh_features, md_w0, Ptop, Pbot, acc, Nn, nb_edge);
    edge_mlp_kernel<<<nb_edge, 256, SMEM>>>(Ptop, Pbot, md_b0, md_wh, md_bh,
                                            srcp, dstp, acc, E);
    dec_md_kernel<<<nb_dec, 256>>>(acc, md_dw1, md_db1, md_dw2, md_db2, meshh, Nn);

    // ---- timesteps ----
    for (int t = 1; t < NTS; t++) {
        const float* fprev_in = (t == 1) ? F_initial : (const float*)Fprev;
        encproj_ds_kernel<<<nb_dec, 256>>>(meshh, fprev_in, F_boundary, t,
                                           ds_encw, ds_encb, ds_w0,
                                           Ptop, Pbot, acc, Nn, nb_edge);
        edge_mlp_kernel<<<nb_edge, 256, SMEM>>>(Ptop, Pbot, ds_b0, ds_wh, ds_bh,
                                                srcp, dstp, acc, E);
        dec_ds_kernel<<<nb_dec, 256>>>(acc, ds_dw1, ds_db1, ds_dw2, ds_db2,
                                       fprev_in, dtp, Fprev, outF, outFd,
                                       t - 1, nsteps, Nn);
    }
}